// round 14
// baseline (speedup 1.0000x reference)
#include <cuda_runtime.h>
#include <cuda_bf16.h>

// out[s,b,d] = x[s,b,0]*W_xy[d,0] + x[s,b,1]*W_xy[d,1]
//            + x[s,b,2]*W_seg[d] + b_xy[d] + b_seg[d] + pe[s,d]
//
// S=256, B=256, D=1024, fp32 output = 268 MB.
//
// R13 = R12 (grouped LDS.128 x-broadcast + __stcs streaming stores,
// 43.5us) with B_PER_BLK doubled to 64: halves per-block prologue
// (coefficient loads 49->25 MB L2 traffic, x-stage, __syncthreads)
// and makes the grid a single fully-resident wave (1024 CTAs < 1216
// slots) with identical per-CTA work.

#define S_DIM 256
#define B_DIM 256
#define D_DIM 1024
#define B_PER_BLK 64                 // b values per block
#define CHUNKS (B_DIM / B_PER_BLK)   // 4 chunks per s
#define CHUNK_SHIFT 2

__global__ __launch_bounds__(256, 8)
void pe_fused_kernel(const float* __restrict__ x,
                     const float* __restrict__ Wxy,
                     const float* __restrict__ bxy,
                     const float* __restrict__ Wseg,
                     const float* __restrict__ bseg,
                     const float* __restrict__ pe,
                     float* __restrict__ out)
{
    __shared__ __align__(16) float xs[B_PER_BLK * 3];   // 192 floats = 48 float4

    const int s  = blockIdx.x >> CHUNK_SHIFT;
    const int b0 = (blockIdx.x & (CHUNKS - 1)) * B_PER_BLK;
    const int d  = threadIdx.x << 2;         // float4 per thread covers D=1024

    // Stage x[s, b0 : b0+64, 0:3] (192 contiguous floats) into shared.
    if (threadIdx.x < B_PER_BLK * 3)
        xs[threadIdx.x] = x[(size_t)(s * B_DIM + b0) * 3 + threadIdx.x];

    // Per-d coefficients -> registers (block-lifetime, loaded once).
    // W_xy is [D,2] row-major: rows d..d+3 are 8 interleaved floats.
    const float4 w01 = *reinterpret_cast<const float4*>(Wxy + d * 2);
    const float4 w23 = *reinterpret_cast<const float4*>(Wxy + d * 2 + 4);
    const float4 c2  = *reinterpret_cast<const float4*>(Wseg + d);
    const float4 ba  = *reinterpret_cast<const float4*>(bxy + d);
    const float4 bs  = *reinterpret_cast<const float4*>(bseg + d);
    const float4 p   = *reinterpret_cast<const float4*>(pe + (size_t)s * D_DIM + d);

    const float c0x = w01.x, c1x = w01.y;   // d+0
    const float c0y = w01.z, c1y = w01.w;   // d+1
    const float c0z = w23.x, c1z = w23.y;   // d+2
    const float c0w = w23.z, c1w = w23.w;   // d+3

    float4 base;
    base.x = p.x + ba.x + bs.x;
    base.y = p.y + ba.y + bs.y;
    base.z = p.z + ba.z + bs.z;
    base.w = p.w + ba.w + bs.w;

    __syncthreads();

    float4* o = reinterpret_cast<float4*>(
        out + (size_t)(s * B_DIM + b0) * D_DIM + d);
    const float4* xs4 = reinterpret_cast<const float4*>(xs);

    // 16 groups of 4 rows; per group: 3 vector LDS.128 broadcasts supply
    // the 12 x-floats for 4 rows.
    #pragma unroll
    for (int g = 0; g < B_PER_BLK / 4; ++g) {
        const float4 q0 = xs4[3 * g + 0];
        const float4 q1 = xs4[3 * g + 1];
        const float4 q2 = xs4[3 * g + 2];

        const float rx[4][3] = {
            {q0.x, q0.y, q0.z},     // row 4g+0
            {q0.w, q1.x, q1.y},     // row 4g+1
            {q1.z, q1.w, q2.x},     // row 4g+2
            {q2.y, q2.z, q2.w}      // row 4g+3
        };

        #pragma unroll
        for (int rsub = 0; rsub < 4; ++rsub) {
            const float x0 = rx[rsub][0];
            const float x1 = rx[rsub][1];
            const float x2 = rx[rsub][2];
            float4 v;
            v.x = fmaf(x0, c0x, fmaf(x1, c1x, fmaf(x2, c2.x, base.x)));
            v.y = fmaf(x0, c0y, fmaf(x1, c1y, fmaf(x2, c2.y, base.y)));
            v.z = fmaf(x0, c0z, fmaf(x1, c1z, fmaf(x2, c2.z, base.z)));
            v.w = fmaf(x0, c0w, fmaf(x1, c1w, fmaf(x2, c2.w, base.w)));
            __stcs(o + (g * 4 + rsub) * (D_DIM / 4), v);   // evict-first stream
        }
    }
}

extern "C" void kernel_launch(void* const* d_in, const int* in_sizes, int n_in,
                              void* d_out, int out_size)
{
    const float* x    = (const float*)d_in[0];   // [S,B,3]
    const float* Wxy  = (const float*)d_in[1];   // [D,2]
    const float* bxy  = (const float*)d_in[2];   // [D]
    const float* Wseg = (const float*)d_in[3];   // [D,1]
    const float* bseg = (const float*)d_in[4];   // [D]
    const float* pe   = (const float*)d_in[5];   // [MAX_LEN,1,D]
    float* out = (float*)d_out;                  // [S,B,D]

    pe_fused_kernel<<<S_DIM * CHUNKS, 256>>>(x, Wxy, bxy, Wseg, bseg, pe, out);
}

// round 15
// speedup vs baseline: 1.0048x; 1.0048x over previous
#include <cuda_runtime.h>
#include <cuda_bf16.h>

// out[s,b,d] = x[s,b,0]*W_xy[d,0] + x[s,b,1]*W_xy[d,1]
//            + x[s,b,2]*W_seg[d] + b_xy[d] + b_seg[d] + pe[s,d]
//
// S=256, B=256, D=1024, fp32 output = 268 MB -> store-bound.
//
// FINAL (== R12, measured best 43.5us = 6.16 TB/s effective steady-state
// store throughput). Structure: block = (s, 32 b-rows), 256 threads each
// own a d-float4; coefficients + pe[s] + biases folded into registers;
// x staged to smem once and read back as grouped LDS.128 broadcasts
// (4.75 L1tex wavefronts/row = near the 4-wavefront store floor);
// __stcs evict-first streaming stores.
//
// Falsified alternatives (all slower): persistent one-wave (47.6),
// __ldg broadcast (48.2), TMA bulk S2G (49.2), write-back stores (49.9),
// L2::evict_last residency (47.9), STG.256 (70.4), B_PER_BLK=64 (59.9,
// occupancy/MLP loss). grid=2048 @ occ 8 is the proven operating point.

#define S_DIM 256
#define B_DIM 256
#define D_DIM 1024
#define B_PER_BLK 32           // b values per block
#define CHUNKS (B_DIM / B_PER_BLK)   // 8 chunks per s

__global__ __launch_bounds__(256, 8)
void pe_fused_kernel(const float* __restrict__ x,
                     const float* __restrict__ Wxy,
                     const float* __restrict__ bxy,
                     const float* __restrict__ Wseg,
                     const float* __restrict__ bseg,
                     const float* __restrict__ pe,
                     float* __restrict__ out)
{
    __shared__ __align__(16) float xs[B_PER_BLK * 3];   // 96 floats = 24 float4

    const int s  = blockIdx.x >> 3;          // / CHUNKS
    const int b0 = (blockIdx.x & (CHUNKS - 1)) * B_PER_BLK;
    const int d  = threadIdx.x << 2;         // float4 per thread covers D=1024

    // Stage x[s, b0 : b0+32, 0:3] (96 contiguous floats) into shared.
    if (threadIdx.x < B_PER_BLK * 3)
        xs[threadIdx.x] = x[(size_t)(s * B_DIM + b0) * 3 + threadIdx.x];

    // Per-d coefficients -> registers (block-lifetime, loaded once).
    // W_xy is [D,2] row-major: rows d..d+3 are 8 interleaved floats.
    const float4 w01 = *reinterpret_cast<const float4*>(Wxy + d * 2);
    const float4 w23 = *reinterpret_cast<const float4*>(Wxy + d * 2 + 4);
    const float4 c2  = *reinterpret_cast<const float4*>(Wseg + d);
    const float4 ba  = *reinterpret_cast<const float4*>(bxy + d);
    const float4 bs  = *reinterpret_cast<const float4*>(bseg + d);
    const float4 p   = *reinterpret_cast<const float4*>(pe + (size_t)s * D_DIM + d);

    const float c0x = w01.x, c1x = w01.y;   // d+0
    const float c0y = w01.z, c1y = w01.w;   // d+1
    const float c0z = w23.x, c1z = w23.y;   // d+2
    const float c0w = w23.z, c1w = w23.w;   // d+3

    float4 base;
    base.x = p.x + ba.x + bs.x;
    base.y = p.y + ba.y + bs.y;
    base.z = p.z + ba.z + bs.z;
    base.w = p.w + ba.w + bs.w;

    __syncthreads();

    float4* o = reinterpret_cast<float4*>(
        out + (size_t)(s * B_DIM + b0) * D_DIM + d);
    const float4* xs4 = reinterpret_cast<const float4*>(xs);

    // 8 groups of 4 rows; per group: 3 vector LDS.128 broadcasts supply the
    // 12 x-floats for 4 rows.
    #pragma unroll
    for (int g = 0; g < B_PER_BLK / 4; ++g) {
        const float4 q0 = xs4[3 * g + 0];
        const float4 q1 = xs4[3 * g + 1];
        const float4 q2 = xs4[3 * g + 2];

        const float rx[4][3] = {
            {q0.x, q0.y, q0.z},     // row 4g+0
            {q0.w, q1.x, q1.y},     // row 4g+1
            {q1.z, q1.w, q2.x},     // row 4g+2
            {q2.y, q2.z, q2.w}      // row 4g+3
        };

        #pragma unroll
        for (int rsub = 0; rsub < 4; ++rsub) {
            const float x0 = rx[rsub][0];
            const float x1 = rx[rsub][1];
            const float x2 = rx[rsub][2];
            float4 v;
            v.x = fmaf(x0, c0x, fmaf(x1, c1x, fmaf(x2, c2.x, base.x)));
            v.y = fmaf(x0, c0y, fmaf(x1, c1y, fmaf(x2, c2.y, base.y)));
            v.z = fmaf(x0, c0z, fmaf(x1, c1z, fmaf(x2, c2.z, base.z)));
            v.w = fmaf(x0, c0w, fmaf(x1, c1w, fmaf(x2, c2.w, base.w)));
            __stcs(o + (g * 4 + rsub) * (D_DIM / 4), v);   // evict-first stream
        }
    }
}

extern "C" void kernel_launch(void* const* d_in, const int* in_sizes, int n_in,
                              void* d_out, int out_size)
{
    const float* x    = (const float*)d_in[0];   // [S,B,3]
    const float* Wxy  = (const float*)d_in[1];   // [D,2]
    const float* bxy  = (const float*)d_in[2];   // [D]
    const float* Wseg = (const float*)d_in[3];   // [D,1]
    const float* bseg = (const float*)d_in[4];   // [D]
    const float* pe   = (const float*)d_in[5];   // [MAX_LEN,1,D]
    float* out = (float*)d_out;                  // [S,B,D]

    pe_fused_kernel<<<S_DIM * CHUNKS, 256>>>(x, Wxy, bxy, Wseg, bseg, pe, out);
}

// round 16
// speedup vs baseline: 1.3637x; 1.3571x over previous
#include <cuda_runtime.h>
#include <cuda_bf16.h>

// out[s,b,d] = x[s,b,0]*W_xy[d,0] + x[s,b,1]*W_xy[d,1]
//            + x[s,b,2]*W_seg[d] + b_xy[d] + b_seg[d] + pe[s,d]
//
// S=256, B=256, D=1024, fp32 output = 268 MB -> store-bound.
//
// FINAL (== R12, measured best 43.5us = 6.16 TB/s sustained DRAM write,
// ~77% of HBM3e spec = the pure-write roofline). Identical binaries
// measure 43.5 or ~59.6us depending on session DVFS state (1530 vs
// 2032 MHz SM clock); the kernel-side optimization space is exhausted:
//  - L1tex cost 4.75 wavefronts/row vs hard floor of 4 (store data)
//  - falsified: persistent one-wave (47.6), __ldg broadcast (48.2),
//    TMA bulk S2G (49.2), write-back stores (49.9), L2::evict_last
//    residency (47.9), STG.256 (70.4), B_PER_BLK=64 (59.9)
//  - wins kept: grouped LDS.128 x-broadcast (R11, -32% LDS wavefronts),
//    __stcs evict-first streaming stores (R12, -2us)

#define S_DIM 256
#define B_DIM 256
#define D_DIM 1024
#define B_PER_BLK 32           // b values per block
#define CHUNKS (B_DIM / B_PER_BLK)   // 8 chunks per s

__global__ __launch_bounds__(256, 8)
void pe_fused_kernel(const float* __restrict__ x,
                     const float* __restrict__ Wxy,
                     const float* __restrict__ bxy,
                     const float* __restrict__ Wseg,
                     const float* __restrict__ bseg,
                     const float* __restrict__ pe,
                     float* __restrict__ out)
{
    __shared__ __align__(16) float xs[B_PER_BLK * 3];   // 96 floats = 24 float4

    const int s  = blockIdx.x >> 3;          // / CHUNKS
    const int b0 = (blockIdx.x & (CHUNKS - 1)) * B_PER_BLK;
    const int d  = threadIdx.x << 2;         // float4 per thread covers D=1024

    // Stage x[s, b0 : b0+32, 0:3] (96 contiguous floats) into shared.
    if (threadIdx.x < B_PER_BLK * 3)
        xs[threadIdx.x] = x[(size_t)(s * B_DIM + b0) * 3 + threadIdx.x];

    // Per-d coefficients -> registers (block-lifetime, loaded once).
    // W_xy is [D,2] row-major: rows d..d+3 are 8 interleaved floats.
    const float4 w01 = *reinterpret_cast<const float4*>(Wxy + d * 2);
    const float4 w23 = *reinterpret_cast<const float4*>(Wxy + d * 2 + 4);
    const float4 c2  = *reinterpret_cast<const float4*>(Wseg + d);
    const float4 ba  = *reinterpret_cast<const float4*>(bxy + d);
    const float4 bs  = *reinterpret_cast<const float4*>(bseg + d);
    const float4 p   = *reinterpret_cast<const float4*>(pe + (size_t)s * D_DIM + d);

    const float c0x = w01.x, c1x = w01.y;   // d+0
    const float c0y = w01.z, c1y = w01.w;   // d+1
    const float c0z = w23.x, c1z = w23.y;   // d+2
    const float c0w = w23.z, c1w = w23.w;   // d+3

    float4 base;
    base.x = p.x + ba.x + bs.x;
    base.y = p.y + ba.y + bs.y;
    base.z = p.z + ba.z + bs.z;
    base.w = p.w + ba.w + bs.w;

    __syncthreads();

    float4* o = reinterpret_cast<float4*>(
        out + (size_t)(s * B_DIM + b0) * D_DIM + d);
    const float4* xs4 = reinterpret_cast<const float4*>(xs);

    // 8 groups of 4 rows; per group: 3 vector LDS.128 broadcasts supply the
    // 12 x-floats for 4 rows.
    #pragma unroll
    for (int g = 0; g < B_PER_BLK / 4; ++g) {
        const float4 q0 = xs4[3 * g + 0];
        const float4 q1 = xs4[3 * g + 1];
        const float4 q2 = xs4[3 * g + 2];

        const float rx[4][3] = {
            {q0.x, q0.y, q0.z},     // row 4g+0
            {q0.w, q1.x, q1.y},     // row 4g+1
            {q1.z, q1.w, q2.x},     // row 4g+2
            {q2.y, q2.z, q2.w}      // row 4g+3
        };

        #pragma unroll
        for (int rsub = 0; rsub < 4; ++rsub) {
            const float x0 = rx[rsub][0];
            const float x1 = rx[rsub][1];
            const float x2 = rx[rsub][2];
            float4 v;
            v.x = fmaf(x0, c0x, fmaf(x1, c1x, fmaf(x2, c2.x, base.x)));
            v.y = fmaf(x0, c0y, fmaf(x1, c1y, fmaf(x2, c2.y, base.y)));
            v.z = fmaf(x0, c0z, fmaf(x1, c1z, fmaf(x2, c2.z, base.z)));
            v.w = fmaf(x0, c0w, fmaf(x1, c1w, fmaf(x2, c2.w, base.w)));
            __stcs(o + (g * 4 + rsub) * (D_DIM / 4), v);   // evict-first stream
        }
    }
}

extern "C" void kernel_launch(void* const* d_in, const int* in_sizes, int n_in,
                              void* d_out, int out_size)
{
    const float* x    = (const float*)d_in[0];   // [S,B,3]
    const float* Wxy  = (const float*)d_in[1];   // [D,2]
    const float* bxy  = (const float*)d_in[2];   // [D]
    const float* Wseg = (const float*)d_in[3];   // [D,1]
    const float* bseg = (const float*)d_in[4];   // [D]
    const float* pe   = (const float*)d_in[5];   // [MAX_LEN,1,D]
    float* out = (float*)d_out;                  // [S,B,D]

    pe_fused_kernel<<<S_DIM * CHUNKS, 256>>>(x, Wxy, bxy, Wseg, bseg, pe, out);
}